// round 3
// baseline (speedup 1.0000x reference)
#include <cuda_runtime.h>
#include <math.h>

// ---------------------------------------------------------------------------
// InteractionNetwork: 3 MLPs + gather/scatter over a 2M-edge graph.
//   K1: e_msg = R1([x[dst], x[src], edge_attr])   (10->40->40->4) + atomic aggr
//   K2: x_tilde = O([x, aggr])                    (7->40->40->3)
//   K3: out = sigmoid(R2([xt[dst], xt[src], e_msg])) (10->40->40->1)
// fp32 scalar, FMA-pipe-bound by design: weights transposed in SMEM and read
// as broadcast float4 (LDS.128) so LDS instr count ~= FMA/4.
// NOTE: edge_index (int64 in reference) is delivered by the harness as int32.
// ---------------------------------------------------------------------------

constexpr int N_MAX = 100000;
constexpr int E_MAX = 2000000;

__device__ float4 g_emsg[E_MAX];       // 32 MB scratch: per-edge message [E,4]
__device__ float  g_aggr[N_MAX * 4];   // scatter-add target [N,4]
__device__ float  g_xt  [N_MAX * 3];   // updated node features [N,3]

// Load g [rows][cols] row-major into s as transposed [cols][rows].
__device__ __forceinline__ void load_T(const float* __restrict__ g, float* s,
                                       int rows, int cols, int tid, int nt) {
    for (int i = tid; i < rows * cols; i += nt) {
        int r = i / cols, c = i % cols;
        s[c * rows + r] = g[i];
    }
}

// out[OUT] = sB + in[IN] @ W^T, with W^T staged in shared as [IN][OUT].
// OUT must be a multiple of 4; weight fetches are float4 broadcasts.
template<int IN, int OUT>
__device__ __forceinline__ void dense(const float* in, const float* sWT,
                                      const float* sB, float* out) {
    static_assert(OUT % 4 == 0, "OUT must be multiple of 4");
#pragma unroll
    for (int j = 0; j < OUT; ++j) out[j] = sB[j];
#pragma unroll
    for (int k = 0; k < IN; ++k) {
        const float a = in[k];
#pragma unroll
        for (int j4 = 0; j4 < OUT / 4; ++j4) {
            float4 w = reinterpret_cast<const float4*>(sWT + k * OUT)[j4];
            out[j4 * 4 + 0] = fmaf(w.x, a, out[j4 * 4 + 0]);
            out[j4 * 4 + 1] = fmaf(w.y, a, out[j4 * 4 + 1]);
            out[j4 * 4 + 2] = fmaf(w.z, a, out[j4 * 4 + 2]);
            out[j4 * 4 + 3] = fmaf(w.w, a, out[j4 * 4 + 3]);
        }
    }
}

template<int N>
__device__ __forceinline__ void relu_(float* v) {
#pragma unroll
    for (int i = 0; i < N; ++i) v[i] = fmaxf(v[i], 0.f);
}

__global__ void zero_aggr_kernel(int n4) {
    int i = blockIdx.x * blockDim.x + threadIdx.x;
    if (i < n4) g_aggr[i] = 0.f;
}

// ---------------------------------------------------------------------------
__global__ __launch_bounds__(128)
void edge_msg_kernel(const float* __restrict__ x,
                     const int* __restrict__ ei,
                     const float* __restrict__ eattr,
                     const float* __restrict__ w1, const float* __restrict__ b1,
                     const float* __restrict__ w2, const float* __restrict__ b2,
                     const float* __restrict__ w3, const float* __restrict__ b3,
                     int E) {
    __shared__ __align__(16) float s_w1T[10 * 40];
    __shared__ __align__(16) float s_w2T[40 * 40];
    __shared__ __align__(16) float s_w3T[40 * 4];
    __shared__ float s_b1[40], s_b2[40], s_b3[4];
    const int tid = threadIdx.x;
    load_T(w1, s_w1T, 40, 10, tid, 128);
    load_T(w2, s_w2T, 40, 40, tid, 128);
    load_T(w3, s_w3T, 4, 40, tid, 128);
    if (tid < 40) { s_b1[tid] = b1[tid]; s_b2[tid] = b2[tid]; }
    if (tid < 4)  s_b3[tid] = b3[tid];
    __syncthreads();

    const int e = blockIdx.x * 128 + tid;
    if (e >= E) return;
    const int src = ei[e];
    const int dst = ei[E + e];

    float in[10];
    in[0] = x[dst * 3 + 0]; in[1] = x[dst * 3 + 1]; in[2] = x[dst * 3 + 2];
    in[3] = x[src * 3 + 0]; in[4] = x[src * 3 + 1]; in[5] = x[src * 3 + 2];
    const float4 ea = reinterpret_cast<const float4*>(eattr)[e];
    in[6] = ea.x; in[7] = ea.y; in[8] = ea.z; in[9] = ea.w;

    float h1[40]; dense<10, 40>(in, s_w1T, s_b1, h1); relu_<40>(h1);
    float h2[40]; dense<40, 40>(h1, s_w2T, s_b2, h2); relu_<40>(h2);
    float o[4];   dense<40, 4>(h2, s_w3T, s_b3, o);

    g_emsg[e] = make_float4(o[0], o[1], o[2], o[3]);
    atomicAdd(&g_aggr[dst * 4 + 0], o[0]);
    atomicAdd(&g_aggr[dst * 4 + 1], o[1]);
    atomicAdd(&g_aggr[dst * 4 + 2], o[2]);
    atomicAdd(&g_aggr[dst * 4 + 3], o[3]);
}

// ---------------------------------------------------------------------------
__global__ __launch_bounds__(128)
void node_kernel(const float* __restrict__ x,
                 const float* __restrict__ w1, const float* __restrict__ b1,
                 const float* __restrict__ w2, const float* __restrict__ b2,
                 const float* __restrict__ w3, const float* __restrict__ b3,
                 int N) {
    __shared__ __align__(16) float s_w1T[7 * 40];
    __shared__ __align__(16) float s_w2T[40 * 40];
    __shared__ __align__(16) float s_w3[3 * 40];   // untransposed: 3 row-dots
    __shared__ float s_b1[40], s_b2[40], s_b3[3];
    const int tid = threadIdx.x;
    load_T(w1, s_w1T, 40, 7, tid, 128);
    load_T(w2, s_w2T, 40, 40, tid, 128);
    for (int i = tid; i < 120; i += 128) s_w3[i] = w3[i];
    if (tid < 40) { s_b1[tid] = b1[tid]; s_b2[tid] = b2[tid]; }
    if (tid < 3)  s_b3[tid] = b3[tid];
    __syncthreads();

    const int n = blockIdx.x * 128 + tid;
    if (n >= N) return;

    float in[7];
    in[0] = x[n * 3 + 0]; in[1] = x[n * 3 + 1]; in[2] = x[n * 3 + 2];
    const float4 ag = reinterpret_cast<const float4*>(g_aggr)[n];
    in[3] = ag.x; in[4] = ag.y; in[5] = ag.z; in[6] = ag.w;

    float h1[40]; dense<7, 40>(in, s_w1T, s_b1, h1); relu_<40>(h1);
    float h2[40]; dense<40, 40>(h1, s_w2T, s_b2, h2); relu_<40>(h2);

#pragma unroll
    for (int j = 0; j < 3; ++j) {
        float acc = s_b3[j];
#pragma unroll
        for (int k4 = 0; k4 < 10; ++k4) {
            float4 w = reinterpret_cast<const float4*>(s_w3 + j * 40)[k4];
            acc = fmaf(w.x, h2[k4 * 4 + 0], acc);
            acc = fmaf(w.y, h2[k4 * 4 + 1], acc);
            acc = fmaf(w.z, h2[k4 * 4 + 2], acc);
            acc = fmaf(w.w, h2[k4 * 4 + 3], acc);
        }
        g_xt[n * 3 + j] = acc;
    }
}

// ---------------------------------------------------------------------------
__global__ __launch_bounds__(128)
void edge_out_kernel(const int* __restrict__ ei,
                     const float* __restrict__ w1, const float* __restrict__ b1,
                     const float* __restrict__ w2, const float* __restrict__ b2,
                     const float* __restrict__ w3, const float* __restrict__ b3,
                     float* __restrict__ out, int E) {
    __shared__ __align__(16) float s_w1T[10 * 40];
    __shared__ __align__(16) float s_w2T[40 * 40];
    __shared__ __align__(16) float s_w3[40];
    __shared__ float s_b1[40], s_b2[40], s_b3s[1];
    const int tid = threadIdx.x;
    load_T(w1, s_w1T, 40, 10, tid, 128);
    load_T(w2, s_w2T, 40, 40, tid, 128);
    if (tid < 40) { s_w3[tid] = w3[tid]; s_b1[tid] = b1[tid]; s_b2[tid] = b2[tid]; }
    if (tid == 0) s_b3s[0] = b3[0];
    __syncthreads();

    const int e = blockIdx.x * 128 + tid;
    if (e >= E) return;
    const int src = ei[e];
    const int dst = ei[E + e];

    float in[10];
    in[0] = g_xt[dst * 3 + 0]; in[1] = g_xt[dst * 3 + 1]; in[2] = g_xt[dst * 3 + 2];
    in[3] = g_xt[src * 3 + 0]; in[4] = g_xt[src * 3 + 1]; in[5] = g_xt[src * 3 + 2];
    const float4 em = g_emsg[e];
    in[6] = em.x; in[7] = em.y; in[8] = em.z; in[9] = em.w;

    float h1[40]; dense<10, 40>(in, s_w1T, s_b1, h1); relu_<40>(h1);
    float h2[40]; dense<40, 40>(h1, s_w2T, s_b2, h2); relu_<40>(h2);

    float acc = s_b3s[0];
#pragma unroll
    for (int k4 = 0; k4 < 10; ++k4) {
        float4 w = reinterpret_cast<const float4*>(s_w3)[k4];
        acc = fmaf(w.x, h2[k4 * 4 + 0], acc);
        acc = fmaf(w.y, h2[k4 * 4 + 1], acc);
        acc = fmaf(w.z, h2[k4 * 4 + 2], acc);
        acc = fmaf(w.w, h2[k4 * 4 + 3], acc);
    }
    out[e] = 1.f / (1.f + expf(-acc));
}

// ---------------------------------------------------------------------------
extern "C" void kernel_launch(void* const* d_in, const int* in_sizes, int n_in,
                              void* d_out, int out_size) {
    const float* x     = (const float*)d_in[0];
    const int*   ei    = (const int*)d_in[1];
    const float* eattr = (const float*)d_in[2];
    const float *r1w1 = (const float*)d_in[3],  *r1b1 = (const float*)d_in[4];
    const float *r1w2 = (const float*)d_in[5],  *r1b2 = (const float*)d_in[6];
    const float *r1w3 = (const float*)d_in[7],  *r1b3 = (const float*)d_in[8];
    const float *ow1  = (const float*)d_in[9],  *ob1  = (const float*)d_in[10];
    const float *ow2  = (const float*)d_in[11], *ob2  = (const float*)d_in[12];
    const float *ow3  = (const float*)d_in[13], *ob3  = (const float*)d_in[14];
    const float *r2w1 = (const float*)d_in[15], *r2b1 = (const float*)d_in[16];
    const float *r2w2 = (const float*)d_in[17], *r2b2 = (const float*)d_in[18];
    const float *r2w3 = (const float*)d_in[19], *r2b3 = (const float*)d_in[20];

    const int N = in_sizes[0] / 3;
    const int E = in_sizes[2] / 4;

    zero_aggr_kernel<<<(N * 4 + 255) / 256, 256>>>(N * 4);
    edge_msg_kernel<<<(E + 127) / 128, 128>>>(x, ei, eattr,
                                              r1w1, r1b1, r1w2, r1b2, r1w3, r1b3, E);
    node_kernel<<<(N + 127) / 128, 128>>>(x, ow1, ob1, ow2, ob2, ow3, ob3, N);
    edge_out_kernel<<<(E + 127) / 128, 128>>>(ei, r2w1, r2b1, r2w2, r2b2, r2w3, r2b3,
                                              (float*)d_out, E);
}

// round 4
// speedup vs baseline: 1.0546x; 1.0546x over previous
#include <cuda_runtime.h>
#include <math.h>

// ---------------------------------------------------------------------------
// InteractionNetwork: 3 MLPs + gather/scatter over a 2M-edge graph.
// R3 finding: LDS.128 broadcast of shared weights has an effective 4 cyc/warp
// crossbar floor -> kernel was LDS-bound (L1=90.8%, fma=37.8%).
// Fix: 2 edges per thread so each weight float4 feeds 8 FMAs (balanced pipes).
// ---------------------------------------------------------------------------

constexpr int N_MAX = 100000;
constexpr int E_MAX = 2000000;

__device__ float4 g_emsg[E_MAX];       // per-edge message [E,4]
__device__ float  g_aggr[N_MAX * 4];   // scatter-add target [N,4]
__device__ float  g_xt  [N_MAX * 3];   // updated node features [N,3]

__device__ __forceinline__ void load_T(const float* __restrict__ g, float* s,
                                       int rows, int cols, int tid, int nt) {
    for (int i = tid; i < rows * cols; i += nt) {
        int r = i / cols, c = i % cols;
        s[c * rows + r] = g[i];
    }
}

// Two independent samples through one dense layer, sharing each weight fetch.
template<int IN, int OUT>
__device__ __forceinline__ void dense2(const float* inA, const float* inB,
                                       const float* sWT, const float* sB,
                                       float* outA, float* outB) {
    static_assert(OUT % 4 == 0, "OUT must be multiple of 4");
#pragma unroll
    for (int j = 0; j < OUT; ++j) { outA[j] = sB[j]; outB[j] = sB[j]; }
#pragma unroll
    for (int k = 0; k < IN; ++k) {
        const float aA = inA[k];
        const float aB = inB[k];
#pragma unroll
        for (int j4 = 0; j4 < OUT / 4; ++j4) {
            float4 w = reinterpret_cast<const float4*>(sWT + k * OUT)[j4];
            outA[j4 * 4 + 0] = fmaf(w.x, aA, outA[j4 * 4 + 0]);
            outA[j4 * 4 + 1] = fmaf(w.y, aA, outA[j4 * 4 + 1]);
            outA[j4 * 4 + 2] = fmaf(w.z, aA, outA[j4 * 4 + 2]);
            outA[j4 * 4 + 3] = fmaf(w.w, aA, outA[j4 * 4 + 3]);
            outB[j4 * 4 + 0] = fmaf(w.x, aB, outB[j4 * 4 + 0]);
            outB[j4 * 4 + 1] = fmaf(w.y, aB, outB[j4 * 4 + 1]);
            outB[j4 * 4 + 2] = fmaf(w.z, aB, outB[j4 * 4 + 2]);
            outB[j4 * 4 + 3] = fmaf(w.w, aB, outB[j4 * 4 + 3]);
        }
    }
}

template<int IN, int OUT>
__device__ __forceinline__ void dense(const float* in, const float* sWT,
                                      const float* sB, float* out) {
    static_assert(OUT % 4 == 0, "OUT must be multiple of 4");
#pragma unroll
    for (int j = 0; j < OUT; ++j) out[j] = sB[j];
#pragma unroll
    for (int k = 0; k < IN; ++k) {
        const float a = in[k];
#pragma unroll
        for (int j4 = 0; j4 < OUT / 4; ++j4) {
            float4 w = reinterpret_cast<const float4*>(sWT + k * OUT)[j4];
            out[j4 * 4 + 0] = fmaf(w.x, a, out[j4 * 4 + 0]);
            out[j4 * 4 + 1] = fmaf(w.y, a, out[j4 * 4 + 1]);
            out[j4 * 4 + 2] = fmaf(w.z, a, out[j4 * 4 + 2]);
            out[j4 * 4 + 3] = fmaf(w.w, a, out[j4 * 4 + 3]);
        }
    }
}

template<int N>
__device__ __forceinline__ void relu_(float* v) {
#pragma unroll
    for (int i = 0; i < N; ++i) v[i] = fmaxf(v[i], 0.f);
}

__global__ void zero_aggr_kernel(int n4) {
    int i = blockIdx.x * blockDim.x + threadIdx.x;
    if (i < n4) g_aggr[i] = 0.f;
}

// ---------------------------------------------------------------------------
// K1: edge message MLP (10->40->40->4) + atomic aggregation. EPT=2.
__global__ __launch_bounds__(128)
void edge_msg_kernel(const float* __restrict__ x,
                     const int* __restrict__ ei,
                     const float* __restrict__ eattr,
                     const float* __restrict__ w1, const float* __restrict__ b1,
                     const float* __restrict__ w2, const float* __restrict__ b2,
                     const float* __restrict__ w3, const float* __restrict__ b3,
                     int E) {
    __shared__ __align__(16) float s_w1T[10 * 40];
    __shared__ __align__(16) float s_w2T[40 * 40];
    __shared__ __align__(16) float s_w3T[40 * 4];
    __shared__ float s_b1[40], s_b2[40], s_b3[4];
    const int tid = threadIdx.x;
    load_T(w1, s_w1T, 40, 10, tid, 128);
    load_T(w2, s_w2T, 40, 40, tid, 128);
    load_T(w3, s_w3T, 4, 40, tid, 128);
    if (tid < 40) { s_b1[tid] = b1[tid]; s_b2[tid] = b2[tid]; }
    if (tid < 4)  s_b3[tid] = b3[tid];
    __syncthreads();

    const int eA = blockIdx.x * 256 + tid;
    const int eB = eA + 128;
    const bool vA = eA < E, vB = eB < E;
    if (!vA) return;

    float inA[10], inB[10];
    int dstA = 0, dstB = 0;
    {
        const int srcA = ei[eA];
        dstA = ei[E + eA];
        inA[0] = x[dstA * 3 + 0]; inA[1] = x[dstA * 3 + 1]; inA[2] = x[dstA * 3 + 2];
        inA[3] = x[srcA * 3 + 0]; inA[4] = x[srcA * 3 + 1]; inA[5] = x[srcA * 3 + 2];
        const float4 ea = reinterpret_cast<const float4*>(eattr)[eA];
        inA[6] = ea.x; inA[7] = ea.y; inA[8] = ea.z; inA[9] = ea.w;
    }
    if (vB) {
        const int srcB = ei[eB];
        dstB = ei[E + eB];
        inB[0] = x[dstB * 3 + 0]; inB[1] = x[dstB * 3 + 1]; inB[2] = x[dstB * 3 + 2];
        inB[3] = x[srcB * 3 + 0]; inB[4] = x[srcB * 3 + 1]; inB[5] = x[srcB * 3 + 2];
        const float4 ea = reinterpret_cast<const float4*>(eattr)[eB];
        inB[6] = ea.x; inB[7] = ea.y; inB[8] = ea.z; inB[9] = ea.w;
    } else {
#pragma unroll
        for (int i = 0; i < 10; ++i) inB[i] = 0.f;
    }

    float h1A[40], h1B[40];
    dense2<10, 40>(inA, inB, s_w1T, s_b1, h1A, h1B);
    relu_<40>(h1A); relu_<40>(h1B);
    float h2A[40], h2B[40];
    dense2<40, 40>(h1A, h1B, s_w2T, s_b2, h2A, h2B);
    relu_<40>(h2A); relu_<40>(h2B);
    float oA[4], oB[4];
    dense2<40, 4>(h2A, h2B, s_w3T, s_b3, oA, oB);

    g_emsg[eA] = make_float4(oA[0], oA[1], oA[2], oA[3]);
    atomicAdd(&g_aggr[dstA * 4 + 0], oA[0]);
    atomicAdd(&g_aggr[dstA * 4 + 1], oA[1]);
    atomicAdd(&g_aggr[dstA * 4 + 2], oA[2]);
    atomicAdd(&g_aggr[dstA * 4 + 3], oA[3]);
    if (vB) {
        g_emsg[eB] = make_float4(oB[0], oB[1], oB[2], oB[3]);
        atomicAdd(&g_aggr[dstB * 4 + 0], oB[0]);
        atomicAdd(&g_aggr[dstB * 4 + 1], oB[1]);
        atomicAdd(&g_aggr[dstB * 4 + 2], oB[2]);
        atomicAdd(&g_aggr[dstB * 4 + 3], oB[3]);
    }
}

// ---------------------------------------------------------------------------
// K2: node update MLP (7->40->40->3). Small (N=100k); EPT=1 is fine.
__global__ __launch_bounds__(128)
void node_kernel(const float* __restrict__ x,
                 const float* __restrict__ w1, const float* __restrict__ b1,
                 const float* __restrict__ w2, const float* __restrict__ b2,
                 const float* __restrict__ w3, const float* __restrict__ b3,
                 int N) {
    __shared__ __align__(16) float s_w1T[7 * 40];
    __shared__ __align__(16) float s_w2T[40 * 40];
    __shared__ __align__(16) float s_w3[3 * 40];   // untransposed: 3 row-dots
    __shared__ float s_b1[40], s_b2[40], s_b3[3];
    const int tid = threadIdx.x;
    load_T(w1, s_w1T, 40, 7, tid, 128);
    load_T(w2, s_w2T, 40, 40, tid, 128);
    for (int i = tid; i < 120; i += 128) s_w3[i] = w3[i];
    if (tid < 40) { s_b1[tid] = b1[tid]; s_b2[tid] = b2[tid]; }
    if (tid < 3)  s_b3[tid] = b3[tid];
    __syncthreads();

    const int n = blockIdx.x * 128 + tid;
    if (n >= N) return;

    float in[7];
    in[0] = x[n * 3 + 0]; in[1] = x[n * 3 + 1]; in[2] = x[n * 3 + 2];
    const float4 ag = reinterpret_cast<const float4*>(g_aggr)[n];
    in[3] = ag.x; in[4] = ag.y; in[5] = ag.z; in[6] = ag.w;

    float h1[40]; dense<7, 40>(in, s_w1T, s_b1, h1); relu_<40>(h1);
    float h2[40]; dense<40, 40>(h1, s_w2T, s_b2, h2); relu_<40>(h2);

#pragma unroll
    for (int j = 0; j < 3; ++j) {
        float acc = s_b3[j];
#pragma unroll
        for (int k4 = 0; k4 < 10; ++k4) {
            float4 w = reinterpret_cast<const float4*>(s_w3 + j * 40)[k4];
            acc = fmaf(w.x, h2[k4 * 4 + 0], acc);
            acc = fmaf(w.y, h2[k4 * 4 + 1], acc);
            acc = fmaf(w.z, h2[k4 * 4 + 2], acc);
            acc = fmaf(w.w, h2[k4 * 4 + 3], acc);
        }
        g_xt[n * 3 + j] = acc;
    }
}

// ---------------------------------------------------------------------------
// K3: edge classifier MLP (10->40->40->1) + sigmoid. EPT=2.
__global__ __launch_bounds__(128)
void edge_out_kernel(const int* __restrict__ ei,
                     const float* __restrict__ w1, const float* __restrict__ b1,
                     const float* __restrict__ w2, const float* __restrict__ b2,
                     const float* __restrict__ w3, const float* __restrict__ b3,
                     float* __restrict__ out, int E) {
    __shared__ __align__(16) float s_w1T[10 * 40];
    __shared__ __align__(16) float s_w2T[40 * 40];
    __shared__ __align__(16) float s_w3[40];
    __shared__ float s_b1[40], s_b2[40], s_b3s[1];
    const int tid = threadIdx.x;
    load_T(w1, s_w1T, 40, 10, tid, 128);
    load_T(w2, s_w2T, 40, 40, tid, 128);
    if (tid < 40) { s_w3[tid] = w3[tid]; s_b1[tid] = b1[tid]; s_b2[tid] = b2[tid]; }
    if (tid == 0) s_b3s[0] = b3[0];
    __syncthreads();

    const int eA = blockIdx.x * 256 + tid;
    const int eB = eA + 128;
    const bool vA = eA < E, vB = eB < E;
    if (!vA) return;

    float inA[10], inB[10];
    {
        const int srcA = ei[eA];
        const int dstA = ei[E + eA];
        inA[0] = g_xt[dstA * 3 + 0]; inA[1] = g_xt[dstA * 3 + 1]; inA[2] = g_xt[dstA * 3 + 2];
        inA[3] = g_xt[srcA * 3 + 0]; inA[4] = g_xt[srcA * 3 + 1]; inA[5] = g_xt[srcA * 3 + 2];
        const float4 em = g_emsg[eA];
        inA[6] = em.x; inA[7] = em.y; inA[8] = em.z; inA[9] = em.w;
    }
    if (vB) {
        const int srcB = ei[eB];
        const int dstB = ei[E + eB];
        inB[0] = g_xt[dstB * 3 + 0]; inB[1] = g_xt[dstB * 3 + 1]; inB[2] = g_xt[dstB * 3 + 2];
        inB[3] = g_xt[srcB * 3 + 0]; inB[4] = g_xt[srcB * 3 + 1]; inB[5] = g_xt[srcB * 3 + 2];
        const float4 em = g_emsg[eB];
        inB[6] = em.x; inB[7] = em.y; inB[8] = em.z; inB[9] = em.w;
    } else {
#pragma unroll
        for (int i = 0; i < 10; ++i) inB[i] = 0.f;
    }

    float h1A[40], h1B[40];
    dense2<10, 40>(inA, inB, s_w1T, s_b1, h1A, h1B);
    relu_<40>(h1A); relu_<40>(h1B);
    float h2A[40], h2B[40];
    dense2<40, 40>(h1A, h1B, s_w2T, s_b2, h2A, h2B);
    relu_<40>(h2A); relu_<40>(h2B);

    float accA = s_b3s[0], accB = s_b3s[0];
#pragma unroll
    for (int k4 = 0; k4 < 10; ++k4) {
        float4 w = reinterpret_cast<const float4*>(s_w3)[k4];
        accA = fmaf(w.x, h2A[k4 * 4 + 0], accA);
        accA = fmaf(w.y, h2A[k4 * 4 + 1], accA);
        accA = fmaf(w.z, h2A[k4 * 4 + 2], accA);
        accA = fmaf(w.w, h2A[k4 * 4 + 3], accA);
        accB = fmaf(w.x, h2B[k4 * 4 + 0], accB);
        accB = fmaf(w.y, h2B[k4 * 4 + 1], accB);
        accB = fmaf(w.z, h2B[k4 * 4 + 2], accB);
        accB = fmaf(w.w, h2B[k4 * 4 + 3], accB);
    }
    out[eA] = 1.f / (1.f + expf(-accA));
    if (vB) out[eB] = 1.f / (1.f + expf(-accB));
}

// ---------------------------------------------------------------------------
extern "C" void kernel_launch(void* const* d_in, const int* in_sizes, int n_in,
                              void* d_out, int out_size) {
    const float* x     = (const float*)d_in[0];
    const int*   ei    = (const int*)d_in[1];
    const float* eattr = (const float*)d_in[2];
    const float *r1w1 = (const float*)d_in[3],  *r1b1 = (const float*)d_in[4];
    const float *r1w2 = (const float*)d_in[5],  *r1b2 = (const float*)d_in[6];
    const float *r1w3 = (const float*)d_in[7],  *r1b3 = (const float*)d_in[8];
    const float *ow1  = (const float*)d_in[9],  *ob1  = (const float*)d_in[10];
    const float *ow2  = (const float*)d_in[11], *ob2  = (const float*)d_in[12];
    const float *ow3  = (const float*)d_in[13], *ob3  = (const float*)d_in[14];
    const float *r2w1 = (const float*)d_in[15], *r2b1 = (const float*)d_in[16];
    const float *r2w2 = (const float*)d_in[17], *r2b2 = (const float*)d_in[18];
    const float *r2w3 = (const float*)d_in[19], *r2b3 = (const float*)d_in[20];

    const int N = in_sizes[0] / 3;
    const int E = in_sizes[2] / 4;

    const int eblk = (E + 255) / 256;   // 256 edges per 128-thread block (EPT=2)
    zero_aggr_kernel<<<(N * 4 + 255) / 256, 256>>>(N * 4);
    edge_msg_kernel<<<eblk, 128>>>(x, ei, eattr,
                                   r1w1, r1b1, r1w2, r1b2, r1w3, r1b3, E);
    node_kernel<<<(N + 127) / 128, 128>>>(x, ow1, ob1, ow2, ob2, ow3, ob3, N);
    edge_out_kernel<<<eblk, 128>>>(ei, r2w1, r2b1, r2w2, r2b2, r2w3, r2b3,
                                   (float*)d_out, E);
}

// round 5
// speedup vs baseline: 1.9877x; 1.8847x over previous
#include <cuda_runtime.h>
#include <math.h>

// ---------------------------------------------------------------------------
// InteractionNetwork. R4 finding: smem-weight broadcast saturates the single
// 128B/cyc L1 port (2:1 over FMA at EPT=1) and EPT=2 fixes the ratio but
// doubles regs -> occupancy/issue bound. R5: weights in __constant__ (uniform
// constant-port loads, zero L1 traffic) + hand-written fma.rn.f32x2 (FFMA2)
// on packed output pairs, EPT=1 for low regs / high occupancy.
// ---------------------------------------------------------------------------

constexpr int N_MAX = 100000;
constexpr int E_MAX = 2000000;

__device__ float4 g_emsg[E_MAX];       // per-edge message [E,4]
__device__ float  g_aggr[N_MAX * 4];   // scatter-add target [N,4]
__device__ float  g_xt  [N_MAX * 3];   // updated node features [N,3]

// --- constant-bank parameter layout (floats, all offsets even) --------------
constexpr int R1W1T = 0;      // [10][40]
constexpr int R1B1  = 400;    // [40]
constexpr int R1W2T = 440;    // [40][40]
constexpr int R1B2  = 2040;   // [40]
constexpr int R1W3T = 2080;   // [40][4]
constexpr int R1B3  = 2240;   // [4]
constexpr int OW1T  = 2244;   // [7][40]
constexpr int OB1   = 2524;   // [40]
constexpr int OW2T  = 2564;   // [40][40]
constexpr int OB2   = 4164;   // [40]
constexpr int OW3T  = 4204;   // [40][4] (4th col zero-pad)
constexpr int OB3   = 4364;   // [4] (pad)
constexpr int R2W1T = 4368;   // [10][40]
constexpr int R2B1  = 4768;   // [40]
constexpr int R2W2T = 4808;   // [40][40]
constexpr int R2B2  = 6408;   // [40]
constexpr int R2W3  = 6448;   // [40]
constexpr int R2B3  = 6488;   // [2]
constexpr int CP_TOTAL = 6496;

__constant__ float cP[CP_TOTAL];
__device__   float g_cparams[CP_TOTAL];   // staging for memcpy-to-symbol

// --- f32x2 packed helpers ---------------------------------------------------
__device__ __forceinline__ void ffma2(unsigned long long& d,
                                      unsigned long long a,
                                      unsigned long long b) {
    asm("fma.rn.f32x2 %0, %1, %2, %0;" : "+l"(d) : "l"(a), "l"(b));
}
__device__ __forceinline__ unsigned long long dup2(float a) {
    unsigned long long r;
    asm("mov.b64 %0, {%1, %1};" : "=l"(r) : "f"(a));
    return r;
}
__device__ __forceinline__ float2 unpack2(unsigned long long v) {
    float2 r;
    asm("mov.b64 {%0, %1}, %2;" : "=f"(r.x), "=f"(r.y) : "l"(v));
    return r;
}

// out[OUT] = cB + in[IN] @ W^T, weights/bias in __constant__, W^T is [IN][OUT].
// Output pairs packed into 64-bit regs; weight pairs load as 64-bit constants.
template<int IN, int OUT, int WOFF, int BOFF>
__device__ __forceinline__ void denseC(const float* in, float* out) {
    static_assert(OUT % 2 == 0, "OUT must be even");
    unsigned long long acc[OUT / 2];
#pragma unroll
    for (int j2 = 0; j2 < OUT / 2; ++j2)
        acc[j2] = *reinterpret_cast<const unsigned long long*>(cP + BOFF + 2 * j2);
#pragma unroll
    for (int k = 0; k < IN; ++k) {
        const unsigned long long a2 = dup2(in[k]);
#pragma unroll
        for (int j2 = 0; j2 < OUT / 2; ++j2) {
            const unsigned long long w2 =
                *reinterpret_cast<const unsigned long long*>(cP + WOFF + k * OUT + 2 * j2);
            ffma2(acc[j2], a2, w2);
        }
    }
#pragma unroll
    for (int j2 = 0; j2 < OUT / 2; ++j2) {
        const float2 v = unpack2(acc[j2]);
        out[2 * j2]     = v.x;
        out[2 * j2 + 1] = v.y;
    }
}

template<int N>
__device__ __forceinline__ void relu_(float* v) {
#pragma unroll
    for (int i = 0; i < N; ++i) v[i] = fmaxf(v[i], 0.f);
}

// ---------------------------------------------------------------------------
// Prep: transpose weights ([OUT][IN] -> [IN][OUT]) + copy biases into staging.
__global__ void prep_params_kernel(
    const float* __restrict__ r1w1, const float* __restrict__ r1b1,
    const float* __restrict__ r1w2, const float* __restrict__ r1b2,
    const float* __restrict__ r1w3, const float* __restrict__ r1b3,
    const float* __restrict__ ow1,  const float* __restrict__ ob1,
    const float* __restrict__ ow2,  const float* __restrict__ ob2,
    const float* __restrict__ ow3,  const float* __restrict__ ob3,
    const float* __restrict__ r2w1, const float* __restrict__ r2b1,
    const float* __restrict__ r2w2, const float* __restrict__ r2b2,
    const float* __restrict__ r2w3, const float* __restrict__ r2b3) {
    const int t = blockIdx.x * blockDim.x + threadIdx.x;
    const int S = gridDim.x * blockDim.x;
    for (int i = t; i < 400;  i += S) { int j = i / 10, k = i % 10; g_cparams[R1W1T + k * 40 + j] = r1w1[i]; }
    for (int i = t; i < 1600; i += S) { int j = i / 40, k = i % 40; g_cparams[R1W2T + k * 40 + j] = r1w2[i]; }
    for (int i = t; i < 160;  i += S) { int j = i / 40, k = i % 40; g_cparams[R1W3T + k * 4 + j]  = r1w3[i]; }
    for (int i = t; i < 280;  i += S) { int j = i / 7,  k = i % 7;  g_cparams[OW1T  + k * 40 + j] = ow1[i];  }
    for (int i = t; i < 1600; i += S) { int j = i / 40, k = i % 40; g_cparams[OW2T  + k * 40 + j] = ow2[i];  }
    for (int i = t; i < 160;  i += S) { int k = i / 4,  j = i % 4;  g_cparams[OW3T + i] = (j < 3) ? ow3[j * 40 + k] : 0.f; }
    for (int i = t; i < 400;  i += S) { int j = i / 10, k = i % 10; g_cparams[R2W1T + k * 40 + j] = r2w1[i]; }
    for (int i = t; i < 1600; i += S) { int j = i / 40, k = i % 40; g_cparams[R2W2T + k * 40 + j] = r2w2[i]; }
    for (int i = t; i < 40;   i += S) {
        g_cparams[R2W3 + i] = r2w3[i];
        g_cparams[R1B1 + i] = r1b1[i]; g_cparams[R1B2 + i] = r1b2[i];
        g_cparams[OB1  + i] = ob1[i];  g_cparams[OB2  + i] = ob2[i];
        g_cparams[R2B1 + i] = r2b1[i]; g_cparams[R2B2 + i] = r2b2[i];
    }
    for (int i = t; i < 4; i += S) {
        g_cparams[R1B3 + i] = r1b3[i];
        g_cparams[OB3  + i] = (i < 3) ? ob3[i] : 0.f;
    }
    if (t == 0) { g_cparams[R2B3] = r2b3[0]; g_cparams[R2B3 + 1] = 0.f; }
}

__global__ void zero_aggr_kernel(int n4) {
    int i = blockIdx.x * blockDim.x + threadIdx.x;
    if (i < n4) g_aggr[i] = 0.f;
}

// ---------------------------------------------------------------------------
// K1: edge message MLP (10->40->40->4) + atomic aggregation.
__global__ __launch_bounds__(256)
void edge_msg_kernel(const float* __restrict__ x,
                     const int* __restrict__ ei,
                     const float* __restrict__ eattr, int E) {
    const int e = blockIdx.x * 256 + threadIdx.x;
    if (e >= E) return;
    const int src = ei[e];
    const int dst = ei[E + e];

    float in[10];
    in[0] = x[dst * 3 + 0]; in[1] = x[dst * 3 + 1]; in[2] = x[dst * 3 + 2];
    in[3] = x[src * 3 + 0]; in[4] = x[src * 3 + 1]; in[5] = x[src * 3 + 2];
    const float4 ea = reinterpret_cast<const float4*>(eattr)[e];
    in[6] = ea.x; in[7] = ea.y; in[8] = ea.z; in[9] = ea.w;

    float h1[40]; denseC<10, 40, R1W1T, R1B1>(in, h1); relu_<40>(h1);
    float h2[40]; denseC<40, 40, R1W2T, R1B2>(h1, h2); relu_<40>(h2);
    float o[4];   denseC<40, 4,  R1W3T, R1B3>(h2, o);

    g_emsg[e] = make_float4(o[0], o[1], o[2], o[3]);
    atomicAdd(&g_aggr[dst * 4 + 0], o[0]);
    atomicAdd(&g_aggr[dst * 4 + 1], o[1]);
    atomicAdd(&g_aggr[dst * 4 + 2], o[2]);
    atomicAdd(&g_aggr[dst * 4 + 3], o[3]);
}

// ---------------------------------------------------------------------------
// K2: node update MLP (7->40->40->3).
__global__ __launch_bounds__(256)
void node_kernel(const float* __restrict__ x, int N) {
    const int n = blockIdx.x * 256 + threadIdx.x;
    if (n >= N) return;

    float in[7];
    in[0] = x[n * 3 + 0]; in[1] = x[n * 3 + 1]; in[2] = x[n * 3 + 2];
    const float4 ag = reinterpret_cast<const float4*>(g_aggr)[n];
    in[3] = ag.x; in[4] = ag.y; in[5] = ag.z; in[6] = ag.w;

    float h1[40]; denseC<7, 40, OW1T, OB1>(in, h1); relu_<40>(h1);
    float h2[40]; denseC<40, 40, OW2T, OB2>(h1, h2); relu_<40>(h2);
    float o[4];   denseC<40, 4,  OW3T, OB3>(h2, o);

    g_xt[n * 3 + 0] = o[0];
    g_xt[n * 3 + 1] = o[1];
    g_xt[n * 3 + 2] = o[2];
}

// ---------------------------------------------------------------------------
// K3: edge classifier MLP (10->40->40->1) + sigmoid.
__global__ __launch_bounds__(256)
void edge_out_kernel(const int* __restrict__ ei,
                     float* __restrict__ out, int E) {
    const int e = blockIdx.x * 256 + threadIdx.x;
    if (e >= E) return;
    const int src = ei[e];
    const int dst = ei[E + e];

    float in[10];
    in[0] = g_xt[dst * 3 + 0]; in[1] = g_xt[dst * 3 + 1]; in[2] = g_xt[dst * 3 + 2];
    in[3] = g_xt[src * 3 + 0]; in[4] = g_xt[src * 3 + 1]; in[5] = g_xt[src * 3 + 2];
    const float4 em = g_emsg[e];
    in[6] = em.x; in[7] = em.y; in[8] = em.z; in[9] = em.w;

    float h1[40]; denseC<10, 40, R2W1T, R2B1>(in, h1); relu_<40>(h1);
    float h2[40]; denseC<40, 40, R2W2T, R2B2>(h1, h2); relu_<40>(h2);

    float acc = cP[R2B3];
#pragma unroll
    for (int k = 0; k < 40; ++k) acc = fmaf(h2[k], cP[R2W3 + k], acc);

    out[e] = 1.f / (1.f + expf(-acc));
}

// ---------------------------------------------------------------------------
extern "C" void kernel_launch(void* const* d_in, const int* in_sizes, int n_in,
                              void* d_out, int out_size) {
    const float* x     = (const float*)d_in[0];
    const int*   ei    = (const int*)d_in[1];
    const float* eattr = (const float*)d_in[2];
    const float *r1w1 = (const float*)d_in[3],  *r1b1 = (const float*)d_in[4];
    const float *r1w2 = (const float*)d_in[5],  *r1b2 = (const float*)d_in[6];
    const float *r1w3 = (const float*)d_in[7],  *r1b3 = (const float*)d_in[8];
    const float *ow1  = (const float*)d_in[9],  *ob1  = (const float*)d_in[10];
    const float *ow2  = (const float*)d_in[11], *ob2  = (const float*)d_in[12];
    const float *ow3  = (const float*)d_in[13], *ob3  = (const float*)d_in[14];
    const float *r2w1 = (const float*)d_in[15], *r2b1 = (const float*)d_in[16];
    const float *r2w2 = (const float*)d_in[17], *r2b2 = (const float*)d_in[18];
    const float *r2w3 = (const float*)d_in[19], *r2b3 = (const float*)d_in[20];

    const int N = in_sizes[0] / 3;
    const int E = in_sizes[2] / 4;

    // Stage transposed params, then copy into the constant bank (D2D, capture-ok).
    prep_params_kernel<<<16, 256>>>(r1w1, r1b1, r1w2, r1b2, r1w3, r1b3,
                                    ow1, ob1, ow2, ob2, ow3, ob3,
                                    r2w1, r2b1, r2w2, r2b2, r2w3, r2b3);
    void* src = nullptr;
    cudaGetSymbolAddress(&src, g_cparams);
    cudaMemcpyToSymbolAsync(cP, src, CP_TOTAL * sizeof(float), 0,
                            cudaMemcpyDeviceToDevice, 0);

    zero_aggr_kernel<<<(N * 4 + 255) / 256, 256>>>(N * 4);
    edge_msg_kernel<<<(E + 255) / 256, 256>>>(x, ei, eattr, E);
    node_kernel<<<(N + 255) / 256, 256>>>(x, N);
    edge_out_kernel<<<(E + 255) / 256, 256>>>(ei, (float*)d_out, E);
}